// round 14
// baseline (speedup 1.0000x reference)
#include <cuda_runtime.h>
#include <cuda_fp16.h>
#include <cstdint>

#define B_ 1024
#define T_ 128

typedef unsigned short u16;
typedef uint32_t u32;

// ---------------- static device buffers ----------------
__device__ __align__(16) u16 W1h[512 * 1024], W1l[512 * 1024];
__device__ __align__(16) u16 W3h[512 * 1024], W3l[512 * 1024];
__device__ __align__(16) u16 Wgh[2048 * 1024], Wgl[2048 * 1024]; // [p=4i+q][k over x|h]
__device__ __align__(16) u16 Hh[2][B_ * 512];
__device__ __align__(16) u16 Ch[B_ * 512];
__device__ __align__(16) u16 Z1h[B_ * 512];
__device__ __align__(16) u16 Xh[B_ * 512];
__device__ __align__(16) u16 Z2h[(size_t)T_ * B_ * 512];
__device__ float g_c[B_ * 512];
__device__ float g_bgp[2048];
__device__ unsigned g_arr2[64];          // two padded barrier counters (chain*32)

// ---------------- helpers ----------------
__device__ __forceinline__ u32 swz(u32 o) { return o ^ ((o >> 3) & 0x70); }
__device__ __forceinline__ u32 s2u(const void* p) {
    u32 a;
    asm("{ .reg .u64 t; cvta.to.shared.u64 t, %1; cvt.u32.u64 %0, t; }" : "=r"(a) : "l"(p));
    return a;
}
__device__ __forceinline__ void cp16(u32 dst, const void* src) {
    asm volatile("cp.async.cg.shared.global [%0], [%1], 16;" :: "r"(dst), "l"(src));
}
__device__ __forceinline__ void cp_commit() { asm volatile("cp.async.commit_group;" ::: "memory"); }
template <int N> __device__ __forceinline__ void cp_wait() {
    asm volatile("cp.async.wait_group %0;" :: "n"(N) : "memory");
}
__device__ __forceinline__ void ldsm4(u32* r, u32 a) {
    asm volatile("ldmatrix.sync.aligned.m8n8.x4.shared.b16 {%0,%1,%2,%3}, [%4];"
                 : "=r"(r[0]), "=r"(r[1]), "=r"(r[2]), "=r"(r[3]) : "r"(a));
}
__device__ __forceinline__ void hmma(float* c, const u32* a, u32 b0, u32 b1) {
    asm volatile("mma.sync.aligned.m16n8k16.row.col.f32.f16.f16.f32 "
                 "{%0,%1,%2,%3}, {%4,%5,%6,%7}, {%8,%9}, {%0,%1,%2,%3};"
                 : "+f"(c[0]), "+f"(c[1]), "+f"(c[2]), "+f"(c[3])
                 : "r"(a[0]), "r"(a[1]), "r"(a[2]), "r"(a[3]), "r"(b0), "r"(b1));
}
__device__ __forceinline__ void splitw(float v, u16& h, u16& l) {
    __half hh = __float2half_rn(v);
    __half ll = __float2half_rn(v - __half2float(hh));
    h = *(u16*)&hh; l = *(u16*)&ll;
}
__device__ __forceinline__ u16 h1(float v) {
    __half x = __float2half_rn(v);
    return *(u16*)&x;
}
__device__ __forceinline__ u32 pack2h(float a, float b) {
    __half2 p = __floats2half2_rn(a, b);
    return *(u32*)&p;
}
__device__ __forceinline__ float sigf(float x) { return 1.f / (1.f + expf(-x)); }

__device__ __forceinline__ void gsync(unsigned* ctr, unsigned& gen, int tid) {
    gen++;
    __syncthreads();
    if (tid == 0) {
        __threadfence();
        atomicAdd(ctr, 1u);
        unsigned tgt = 128u * gen;
        while (atomicAdd(ctr, 0u) < tgt) __nanosleep(64);
        __threadfence();
    }
    __syncthreads();
}

// ---------------- prep: split weights, biases, zero state, reset barriers ----------------
__global__ __launch_bounds__(256) void prep_w(
    const float* __restrict__ W1, const float* __restrict__ W3,
    const float* __restrict__ Wih, const float* __restrict__ Whh,
    const float* __restrict__ bih, const float* __restrict__ bhh)
{
    if (blockIdx.x == 0 && threadIdx.x < 64) g_arr2[threadIdx.x] = 0u;
    const int N1 = 524288, N2 = 1048576, N3 = N2 + 2097152;
    const int N4 = N3 + 2048, N5 = N4 + 524288, N6 = N5 + 524288;
    for (int idx = blockIdx.x * blockDim.x + threadIdx.x; idx < N6;
         idx += gridDim.x * blockDim.x) {
        if (idx < N2) {
            int j = (idx < N1) ? idx : idx - N1;
            float v = (idx < N1) ? W1[j] : W3[j];
            u16 h, l; splitw(v, h, l);
            if (idx < N1) { W1h[j] = h; W1l[j] = l; }
            else          { W3h[j] = h; W3l[j] = l; }
        } else if (idx < N3) {
            int j = idx - N2;
            int p = j >> 10, k = j & 1023;
            int r = (p & 3) * 512 + (p >> 2);
            float v = (k < 512) ? Wih[r * 512 + k] : Whh[r * 512 + (k - 512)];
            u16 h, l; splitw(v, h, l);
            Wgh[j] = h; Wgl[j] = l;
        } else if (idx < N4) {
            int p = idx - N3, i = p >> 2, q = p & 3;
            g_bgp[p] = bih[q * 512 + i] + bhh[q * 512 + i];
        } else if (idx < N5) {
            int j = idx - N4;
            int sel = j >> 18, w = j & 262143;
            u16* b = (sel == 0) ? Hh[0] : Ch;
            *(u32*)&b[w * 2] = 0u;
        } else g_c[idx - N5] = 0.f;
    }
}

// ---------------- prep: z2 for all t (fp16) ----------------
__global__ __launch_bounds__(256) void prep_z2(
    const float* __restrict__ sv, const float* __restrict__ W2, const float* __restrict__ b2)
{
    __shared__ float W2s[10 * 512];
    __shared__ float svs[32 * 10];
    int tid = threadIdx.x;
    for (int idx = tid; idx < 5120; idx += 256)
        W2s[(idx % 10) * 512 + idx / 10] = W2[idx];
    int u0 = blockIdx.x * 32;
    for (int idx = tid; idx < 320; idx += 256) svs[idx] = sv[u0 * 10 + idx];
    __syncthreads();
    int f0 = tid * 2;
    float c0 = b2[f0], c1 = b2[f0 + 1];
    for (int p = 0; p < 32; ++p) {
        int u = u0 + p, bb = u >> 7, tt = u & 127;
        float a0 = c0, a1 = c1;
#pragma unroll
        for (int j = 0; j < 10; ++j) {
            float s = svs[p * 10 + j];
            a0 += s * W2s[j * 512 + f0];
            a1 += s * W2s[j * 512 + f0 + 1];
        }
        size_t off = (size_t)tt * 524288 + (size_t)bb * 512 + f0;
        *(u32*)&Z2h[off] = pack2h(fmaxf(a0, 0.f), fmaxf(a1, 0.f));
    }
}

// ---------------- tile engines ----------------
// small: 64x64 tile, 8 warps (wm 0..1, wn 0..3), NFR=2, k-fragment prefetch
__device__ __forceinline__ void tile_small(
    u32 sb, int tid, int lane, int wm, int wn,
    const u16* __restrict__ A1, const u16* __restrict__ A2,
    const u16* __restrict__ Bh_, const u16* __restrict__ Bl_,
    int m0, int n0, float acc[2][2][4])
{
    constexpr u32 STG = 24576, OBH = 8192, OBL = 16384;
#pragma unroll
    for (int a = 0; a < 2; ++a)
#pragma unroll
        for (int b = 0; b < 2; ++b)
#pragma unroll
            for (int q = 0; q < 4; ++q) acc[a][b][q] = 0.f;

    auto load_stage = [&](int s) {
        int ks = s * 64, kc = ks & 511;
        const u16* sa = (ks < 512) ? A1 : A2;
        u32 base = sb + (u32)(s & 1) * STG;
#pragma unroll
        for (int i = tid; i < 512; i += 256) {
            int row = i >> 3, c16 = i & 7;
            cp16(base + swz((u32)(row * 128 + c16 * 16)),
                 sa + (size_t)(m0 + row) * 512 + kc + c16 * 8);
        }
#pragma unroll
        for (int i = tid; i < 512; i += 256) {
            int row = i >> 3, c16 = i & 7;
            size_t g = (size_t)(n0 + row) * 1024 + ks + c16 * 8;
            u32 d = swz((u32)(row * 128 + c16 * 16));
            cp16(base + OBH + d, Bh_ + g);
            cp16(base + OBL + d, Bl_ + g);
        }
    };
    load_stage(0); cp_commit();

    const int arow = wm * 32 + (lane & 15);
    const int brow = wn * 16 + (lane & 15);
    const u32 hi16 = (u32)((lane >> 4) * 16);

    for (int s = 0; s < 16; ++s) {
        cp_wait<0>();
        __syncthreads();
        if (s + 1 < 16) load_stage(s + 1);
        cp_commit();
        u32 base = sb + (u32)(s & 1) * STG;
        u32 Af[2][2][4], Bhf[2][4], Blf[2][4];
#define LDFRAG_S(bf, kk) do { \
        u32 kb = (u32)((kk) * 32) + hi16; \
        ldsm4(Af[bf][0], base + swz((u32)(arow * 128) + kb)); \
        ldsm4(Af[bf][1], base + swz((u32)((arow + 16) * 128) + kb)); \
        ldsm4(Bhf[bf], base + OBH + swz((u32)(brow * 128) + kb)); \
        ldsm4(Blf[bf], base + OBL + swz((u32)(brow * 128) + kb)); \
    } while (0)
        LDFRAG_S(0, 0);
#pragma unroll
        for (int kk = 0; kk < 4; ++kk) {
            const int cur = kk & 1;
            if (kk < 3) LDFRAG_S(cur ^ 1, kk + 1);
#pragma unroll
            for (int term = 0; term < 2; ++term)
#pragma unroll
                for (int fm = 0; fm < 2; ++fm)
#pragma unroll
                    for (int fn = 0; fn < 2; ++fn) {
                        u32 b0 = term ? Blf[cur][fn] : Bhf[cur][fn];
                        u32 b1 = term ? Blf[cur][fn + 2] : Bhf[cur][fn + 2];
                        hmma(acc[fm][fn], Af[cur][fm], b0, b1);
                    }
        }
#undef LDFRAG_S
    }
}

// gates: 256x32 tile, 8 warps ALL in m (wm=wid), NFR=4
// per chain: 2 m-tiles x 64 n-tiles -> Wg read 2x per chain (32 MB/step total)
__device__ __forceinline__ void tile_gates(
    u32 sb, int tid, int lane, int wm,
    const u16* __restrict__ A1, const u16* __restrict__ A2,
    const u16* __restrict__ Bh_, const u16* __restrict__ Bl_,
    int m0, int n0, float acc[2][4][4])
{
    constexpr u32 STG = 40960, OBH = 32768, OBL = 36864;
#pragma unroll
    for (int a = 0; a < 2; ++a)
#pragma unroll
        for (int b = 0; b < 4; ++b)
#pragma unroll
            for (int q = 0; q < 4; ++q) acc[a][b][q] = 0.f;

    auto load_stage = [&](int s) {
        int ks = s * 64, kc = ks & 511;
        const u16* sa = (ks < 512) ? A1 : A2;
        u32 base = sb + (u32)(s & 1) * STG;
#pragma unroll
        for (int i = tid; i < 2048; i += 256) {          // A: 256 rows
            int row = i >> 3, c16 = i & 7;
            cp16(base + swz((u32)(row * 128 + c16 * 16)),
                 sa + (size_t)(m0 + row) * 512 + kc + c16 * 8);
        }
        { // B: 32 rows hi+lo (256 cp16 total -> one per thread)
            int i = tid;
            int row = (i >> 3) & 31, c16 = i & 7;
            int part = i >> 8;                            // 0 only (tid<256)
            (void)part;
            size_t g = (size_t)(n0 + row) * 1024 + ks + c16 * 8;
            u32 d = swz((u32)(row * 128 + c16 * 16));
            if (i < 256) {
                cp16(base + OBH + d, Bh_ + g);
                cp16(base + OBL + d, Bl_ + g);
            }
        }
    };
    load_stage(0); cp_commit();

    const int arow = wm * 32 + (lane & 15);
    const int brow = lane & 15;
    const u32 hi16 = (u32)((lane >> 4) * 16);

    for (int s = 0; s < 16; ++s) {
        cp_wait<0>();
        __syncthreads();
        if (s + 1 < 16) load_stage(s + 1);
        cp_commit();
        u32 base = sb + (u32)(s & 1) * STG;
#pragma unroll
        for (int kk = 0; kk < 4; ++kk) {
            u32 kb = (u32)(kk * 32) + hi16;
            u32 Ar[2][4], Bhr[2][4], Blr[2][4];
#pragma unroll
            for (int fm = 0; fm < 2; ++fm)
                ldsm4(Ar[fm], base + swz((u32)((arow + fm * 16) * 128) + kb));
#pragma unroll
            for (int nf = 0; nf < 2; ++nf) {
                u32 off = swz((u32)((brow + nf * 16) * 128) + kb);
                ldsm4(Bhr[nf], base + OBH + off);
                ldsm4(Blr[nf], base + OBL + off);
            }
#pragma unroll
            for (int term = 0; term < 2; ++term)
#pragma unroll
                for (int fm = 0; fm < 2; ++fm)
#pragma unroll
                    for (int fn = 0; fn < 4; ++fn) {
                        u32 b0 = term ? Blr[fn >> 1][fn & 1] : Bhr[fn >> 1][fn & 1];
                        u32 b1 = term ? Blr[fn >> 1][(fn & 1) + 2] : Bhr[fn >> 1][(fn & 1) + 2];
                        hmma(acc[fm][fn], Ar[fm], b0, b1);
                    }
        }
    }
}

// ---------------- persistent kernel: 2 independent half-batch chains, 2 CTAs/SM ----------------
__global__ __launch_bounds__(256, 2) void lstm_persist(
    const float* __restrict__ b1, const float* __restrict__ b3,
    float* __restrict__ out)
{
    extern __shared__ __align__(16) unsigned char smem[];
    const u32 sb = s2u(smem);
    const int tid = threadIdx.x, lane = tid & 31, wid = tid >> 5;
    const int wm = wid & 1, wn = wid >> 1;
    const int bid = blockIdx.x;
    const int chain = (bid >= 128);
    const int L = bid - chain * 128;          // 0..127 within chain
    const int mb = chain * 512;               // chain batch base
    unsigned* ctr = &g_arr2[chain * 32];

    // small phases: only L<64 active, 8x8 tiles of 64x64 over 512x512
    const bool sm_act = (L < 64);
    const int m0 = mb + (L >> 3) * 64;
    const int n0s = (L & 7) * 64;
    // gates: all 128 CTAs: 2 m-tiles x 64 n-tiles of 256x32 over 512x2048
    const int m0g = mb + (L >> 6) * 256;
    const int n0g = (L & 63) * 32;
    unsigned gen = 0;

    for (int t = 0; t < T_; ++t) {
        int ping = t & 1;

        if (sm_act) { // phase Z1
            float acc[2][2][4];
            tile_small(sb, tid, lane, wm, wn, Hh[ping], Ch, W1h, W1l, m0, n0s, acc);
#pragma unroll
            for (int fm = 0; fm < 2; ++fm)
#pragma unroll
                for (int fn = 0; fn < 2; ++fn) {
                    int c = n0s + wn * 16 + fn * 8 + (lane & 3) * 2;
                    int r = m0 + wm * 32 + fm * 16 + (lane >> 2);
                    float v0 = b1[c], v1 = b1[c + 1];
                    *(u32*)&Z1h[(size_t)r * 512 + c] =
                        pack2h(fmaxf(acc[fm][fn][0] + v0, 0.f), fmaxf(acc[fm][fn][1] + v1, 0.f));
                    *(u32*)&Z1h[(size_t)(r + 8) * 512 + c] =
                        pack2h(fmaxf(acc[fm][fn][2] + v0, 0.f), fmaxf(acc[fm][fn][3] + v1, 0.f));
                }
        }
        gsync(ctr, gen, tid);

        if (sm_act) { // phase X
            float acc[2][2][4];
            tile_small(sb, tid, lane, wm, wn, Z1h, Z2h + (size_t)t * 524288,
                       W3h, W3l, m0, n0s, acc);
#pragma unroll
            for (int fm = 0; fm < 2; ++fm)
#pragma unroll
                for (int fn = 0; fn < 2; ++fn) {
                    int c = n0s + wn * 16 + fn * 8 + (lane & 3) * 2;
                    int r = m0 + wm * 32 + fm * 16 + (lane >> 2);
                    float v0 = b3[c], v1 = b3[c + 1];
                    *(u32*)&Xh[(size_t)r * 512 + c] =
                        pack2h(fmaxf(acc[fm][fn][0] + v0, 0.f), fmaxf(acc[fm][fn][1] + v1, 0.f));
                    *(u32*)&Xh[(size_t)(r + 8) * 512 + c] =
                        pack2h(fmaxf(acc[fm][fn][2] + v0, 0.f), fmaxf(acc[fm][fn][3] + v1, 0.f));
                }
        }
        gsync(ctr, gen, tid);

        { // phase gates + LSTM cell (all CTAs)
            float acc[2][4][4];
            tile_gates(sb, tid, lane, wid, Xh, Hh[ping], Wgh, Wgl, m0g, n0g, acc);
            u16* hh = Hh[ping ^ 1];
            bool odd = lane & 1;
#pragma unroll
            for (int fm = 0; fm < 2; ++fm)
#pragma unroll
                for (int fn = 0; fn < 4; ++fn) {
                    float v0 = acc[fm][fn][0], v1 = acc[fm][fn][1];
                    float v2 = acc[fm][fn][2], v3 = acc[fm][fn][3];
                    float s0 = __shfl_xor_sync(0xFFFFFFFFu, v0, 1);
                    float s1 = __shfl_xor_sync(0xFFFFFFFFu, v1, 1);
                    float s2 = __shfl_xor_sync(0xFFFFFFFFu, v2, 1);
                    float s3 = __shfl_xor_sync(0xFFFFFFFFu, v3, 1);
                    int p = n0g + fn * 8 + (lane & 3) * 2;
                    int u = p >> 2;
                    int row = m0g + wid * 32 + fm * 16 + (lane >> 2) + (odd ? 8 : 0);
                    float gi = odd ? s2 : v0;
                    float gf = odd ? s3 : v1;
                    float gg = odd ? v2 : s0;
                    float go = odd ? v3 : s1;
                    int pb = u * 4;
                    gi += g_bgp[pb];     gf += g_bgp[pb + 1];
                    gg += g_bgp[pb + 2]; go += g_bgp[pb + 3];
                    float I = sigf(gi), F = sigf(gf), G = tanhf(gg), O = sigf(go);
                    size_t ix = (size_t)row * 512 + u;
                    float cn = F * g_c[ix] + I * G;
                    float hn = O * tanhf(cn);
                    g_c[ix] = cn;
                    out[((size_t)row * T_ + t) * 512 + u] = hn;
                    hh[ix] = h1(hn);
                    Ch[ix] = h1(cn);
                }
        }
        gsync(ctr, gen, tid);
    }
}

// ---------------- launch ----------------
extern "C" void kernel_launch(void* const* d_in, const int* in_sizes, int n_in,
                              void* d_out, int out_size)
{
    const float* sv  = (const float*)d_in[0];
    const float* W1  = (const float*)d_in[1];
    const float* b1  = (const float*)d_in[2];
    const float* W2  = (const float*)d_in[3];
    const float* b2  = (const float*)d_in[4];
    const float* W3  = (const float*)d_in[5];
    const float* b3  = (const float*)d_in[6];
    const float* Wih = (const float*)d_in[7];
    const float* Whh = (const float*)d_in[8];
    const float* bih = (const float*)d_in[9];
    const float* bhh = (const float*)d_in[10];
    float* out = (float*)d_out;

    const int SMEM = 2 * 40960;   // 81920 (gates stage is the max)
    static bool init = false;
    if (!init) {
        init = true;
        cudaFuncSetAttribute(lstm_persist, cudaFuncAttributeMaxDynamicSharedMemorySize, SMEM);
    }

    prep_w<<<2048, 256>>>(W1, W3, Wih, Whh, bih, bhh);
    prep_z2<<<4096, 256>>>(sv, W2, b2);
    lstm_persist<<<256, 256, SMEM>>>(b1, b3, out);
}

// round 15
// speedup vs baseline: 1.6550x; 1.6550x over previous
#include <cuda_runtime.h>
#include <cuda_fp16.h>
#include <cstdint>

#define B_ 1024
#define T_ 128

typedef unsigned short u16;
typedef uint32_t u32;

// ---------------- static device buffers (fp16 everywhere, single-term weights) ----------------
__device__ __align__(16) u16 W1h[512 * 1024];
__device__ __align__(16) u16 W3h[512 * 1024];
__device__ __align__(16) u16 Wgh[2048 * 1024];   // [p=4i+q][k over x|h]
__device__ __align__(16) u16 Hh[2][B_ * 512];
__device__ __align__(16) u16 Ch[B_ * 512];
__device__ __align__(16) u16 Z1h[B_ * 512];
__device__ __align__(16) u16 Xh[B_ * 512];
__device__ __align__(16) u16 Z2h[(size_t)T_ * B_ * 512];
__device__ float g_c[B_ * 512];     // fp32 master cell state
__device__ float g_bgp[2048];

// ---------------- helpers ----------------
__device__ __forceinline__ u32 swz(u32 o) { return o ^ ((o >> 3) & 0x70); }
__device__ __forceinline__ u32 s2u(const void* p) {
    u32 a;
    asm("{ .reg .u64 t; cvta.to.shared.u64 t, %1; cvt.u32.u64 %0, t; }" : "=r"(a) : "l"(p));
    return a;
}
__device__ __forceinline__ void cp16(u32 dst, const void* src) {
    asm volatile("cp.async.cg.shared.global [%0], [%1], 16;" :: "r"(dst), "l"(src));
}
__device__ __forceinline__ void cp_commit() { asm volatile("cp.async.commit_group;" ::: "memory"); }
template <int N> __device__ __forceinline__ void cp_wait() {
    asm volatile("cp.async.wait_group %0;" :: "n"(N) : "memory");
}
__device__ __forceinline__ void ldsm4(u32* r, u32 a) {
    asm volatile("ldmatrix.sync.aligned.m8n8.x4.shared.b16 {%0,%1,%2,%3}, [%4];"
                 : "=r"(r[0]), "=r"(r[1]), "=r"(r[2]), "=r"(r[3]) : "r"(a));
}
__device__ __forceinline__ void hmma(float* c, const u32* a, u32 b0, u32 b1) {
    asm volatile("mma.sync.aligned.m16n8k16.row.col.f32.f16.f16.f32 "
                 "{%0,%1,%2,%3}, {%4,%5,%6,%7}, {%8,%9}, {%0,%1,%2,%3};"
                 : "+f"(c[0]), "+f"(c[1]), "+f"(c[2]), "+f"(c[3])
                 : "r"(a[0]), "r"(a[1]), "r"(a[2]), "r"(a[3]), "r"(b0), "r"(b1));
}
__device__ __forceinline__ u16 h1(float v) {
    __half x = __float2half_rn(v);
    return *(u16*)&x;
}
__device__ __forceinline__ u32 pack2h(float a, float b) {
    __half2 p = __floats2half2_rn(a, b);
    return *(u32*)&p;
}
__device__ __forceinline__ float sigf(float x) { return 1.f / (1.f + expf(-x)); }

// ---------------- prep: fp16 weights, biases, zero state ----------------
__global__ __launch_bounds__(256) void prep_w(
    const float* __restrict__ W1, const float* __restrict__ W3,
    const float* __restrict__ Wih, const float* __restrict__ Whh,
    const float* __restrict__ bih, const float* __restrict__ bhh)
{
    const int N1 = 524288, N2 = 1048576, N3 = N2 + 2097152;
    const int N4 = N3 + 2048, N5 = N4 + 524288, N6 = N5 + 524288;
    for (int idx = blockIdx.x * blockDim.x + threadIdx.x; idx < N6;
         idx += gridDim.x * blockDim.x) {
        if (idx < N2) {
            int j = (idx < N1) ? idx : idx - N1;
            float v = (idx < N1) ? W1[j] : W3[j];
            if (idx < N1) W1h[j] = h1(v); else W3h[j] = h1(v);
        } else if (idx < N3) {
            int j = idx - N2;
            int p = j >> 10, k = j & 1023;
            int r = (p & 3) * 512 + (p >> 2);
            float v = (k < 512) ? Wih[r * 512 + k] : Whh[r * 512 + (k - 512)];
            Wgh[j] = h1(v);
        } else if (idx < N4) {
            int p = idx - N3, i = p >> 2, q = p & 3;
            g_bgp[p] = bih[q * 512 + i] + bhh[q * 512 + i];
        } else if (idx < N5) {
            int j = idx - N4;
            int sel = j >> 18, w = j & 262143;
            u16* b = (sel == 0) ? Hh[0] : Ch;
            *(u32*)&b[w * 2] = 0u;
        } else g_c[idx - N5] = 0.f;
    }
}

// ---------------- prep: z2 for all t (fp16) ----------------
__global__ __launch_bounds__(256) void prep_z2(
    const float* __restrict__ sv, const float* __restrict__ W2, const float* __restrict__ b2)
{
    __shared__ float W2s[10 * 512];
    __shared__ float svs[32 * 10];
    int tid = threadIdx.x;
    for (int idx = tid; idx < 5120; idx += 256)
        W2s[(idx % 10) * 512 + idx / 10] = W2[idx];
    int u0 = blockIdx.x * 32;
    for (int idx = tid; idx < 320; idx += 256) svs[idx] = sv[u0 * 10 + idx];
    __syncthreads();
    int f0 = tid * 2;
    float c0 = b2[f0], c1 = b2[f0 + 1];
    for (int p = 0; p < 32; ++p) {
        int u = u0 + p, bb = u >> 7, tt = u & 127;
        float a0 = c0, a1 = c1;
#pragma unroll
        for (int j = 0; j < 10; ++j) {
            float s = svs[p * 10 + j];
            a0 += s * W2s[j * 512 + f0];
            a1 += s * W2s[j * 512 + f0 + 1];
        }
        size_t off = (size_t)tt * 524288 + (size_t)bb * 512 + f0;
        *(u32*)&Z2h[off] = pack2h(fmaxf(a0, 0.f), fmaxf(a1, 0.f));
    }
}

// ---------------- single-term fp16 HMMA GEMM ----------------
// MODE 0: z1 = relu([h|c] @ W1^T + b1)      tile 32x64, 128thr, 3-stage, grid (16,8)
// MODE 1: x  = relu([z1|z2_t] @ W3^T + b3)  tile 32x64, 128thr, 3-stage, grid (16,8)
// MODE 2: gates(interleaved) + LSTM cell    tile 128x64, 256thr, 2-stage, grid (4,32)
template <int MODE>
__global__ __launch_bounds__((MODE == 2) ? 256 : 128, 1) void gemm_mma(
    int m0g, int ping, int t, const float* __restrict__ bias, float* __restrict__ out)
{
    constexpr int MT  = (MODE == 2) ? 128 : 32;
    constexpr int TH  = (MODE == 2) ? 256 : 128;
    constexpr int NWARP = TH / 32;
    constexpr int WMW = (MODE == 2) ? 4 : 1;
    constexpr int WNW = NWARP / WMW;
    constexpr int NFR = 8 / WNW;
    constexpr int NSTAGE = (MODE == 2) ? 2 : 3;
    constexpr int AH = 0, BH = MT * 128;
    constexpr int STAGE = MT * 128 + 8192;

    extern __shared__ __align__(16) unsigned char smem[];
    const u32 sb = s2u(smem);
    const int tid = threadIdx.x, lane = tid & 31, wid = tid >> 5;
    const int m0 = m0g + blockIdx.x * MT, n0 = blockIdx.y * 64;
    const int wm = wid % WMW, wn = wid / WMW;

    const u16 *A1, *A2, *Wh;
    if (MODE == 0) { A1 = Hh[ping]; A2 = Ch; Wh = W1h; }
    else if (MODE == 1) {
        A1 = Z1h; A2 = Z2h + (size_t)t * 524288; Wh = W3h;
    } else { A1 = Xh; A2 = Hh[ping]; Wh = Wgh; }

    float acc[2][NFR][4];
#pragma unroll
    for (int a = 0; a < 2; ++a)
#pragma unroll
        for (int b = 0; b < NFR; ++b)
#pragma unroll
            for (int q = 0; q < 4; ++q) acc[a][b][q] = 0.f;

    auto load_stage = [&](int s) {
        int buf = s % NSTAGE, ks = s * 64, kc = ks & 511;
        const u16* sa = (ks < 512) ? A1 : A2;
        u32 base = sb + (u32)buf * STAGE;
#pragma unroll
        for (int i = tid; i < MT * 8; i += TH) {
            int row = i >> 3, c16 = i & 7;
            cp16(base + AH + swz((u32)(row * 128 + c16 * 16)),
                 sa + (size_t)(m0 + row) * 512 + kc + c16 * 8);
        }
#pragma unroll
        for (int i = tid; i < 512; i += TH) {
            int row = i >> 3, c16 = i & 7;
            cp16(base + BH + swz((u32)(row * 128 + c16 * 16)),
                 Wh + (size_t)(n0 + row) * 1024 + ks + c16 * 8);
        }
    };

#pragma unroll
    for (int s = 0; s < NSTAGE - 1; ++s) { load_stage(s); cp_commit(); }

    const int arow = wm * 32 + (lane & 15);
    const int brow = wn * (NFR * 8) + (lane & 15);
    const u32 hi16 = (u32)((lane >> 4) * 16);

    for (int s = 0; s < 16; ++s) {
        cp_wait<NSTAGE - 2>();
        __syncthreads();
        if (s + NSTAGE - 1 < 16) load_stage(s + NSTAGE - 1);
        cp_commit();   // unconditional: tail-drain-safe group alignment
        u32 base = sb + (u32)(s % NSTAGE) * STAGE;

        if (MODE == 2) {
#pragma unroll
            for (int kk = 0; kk < 4; ++kk) {
                u32 kb = (u32)(kk * 32) + hi16;
                u32 Ar[2][4], Br[2][4];
#pragma unroll
                for (int fm = 0; fm < 2; ++fm)
                    ldsm4(Ar[fm], base + AH + swz((u32)((arow + fm * 16) * 128) + kb));
#pragma unroll
                for (int nf = 0; nf < 2; ++nf)
                    ldsm4(Br[nf], base + BH + swz((u32)((brow + nf * 16) * 128) + kb));
#pragma unroll
                for (int fm = 0; fm < 2; ++fm)
#pragma unroll
                    for (int fn = 0; fn < 4; ++fn)
                        hmma(acc[fm][fn], Ar[fm],
                             Br[fn >> 1][fn & 1], Br[fn >> 1][(fn & 1) + 2]);
            }
        } else {
            u32 Af[2][2][4], Bf[2][4];
#define LDFRAG(bf, kk) do { \
            u32 kb = (u32)((kk) * 32) + hi16; \
            ldsm4(Af[bf][0], base + AH + swz((u32)(arow * 128) + kb)); \
            ldsm4(Af[bf][1], base + AH + swz((u32)((arow + 16) * 128) + kb)); \
            ldsm4(Bf[bf], base + BH + swz((u32)(brow * 128) + kb)); \
        } while (0)
            LDFRAG(0, 0);
#pragma unroll
            for (int kk = 0; kk < 4; ++kk) {
                const int cur = kk & 1;
                if (kk < 3) LDFRAG(cur ^ 1, kk + 1);
#pragma unroll
                for (int fm = 0; fm < 2; ++fm)
#pragma unroll
                    for (int fn = 0; fn < 2; ++fn)
                        hmma(acc[fm][fn], Af[cur][fm], Bf[cur][fn], Bf[cur][fn + 2]);
            }
#undef LDFRAG
        }
    }

    // ---------------- epilogue ----------------
    if (MODE < 2) {
        u16* Dh = (MODE == 0) ? Z1h : Xh;
#pragma unroll
        for (int fm = 0; fm < 2; ++fm)
#pragma unroll
            for (int fn = 0; fn < NFR; ++fn) {
                int c = n0 + wn * (NFR * 8) + fn * 8 + (lane & 3) * 2;
                int r = m0 + wm * 32 + fm * 16 + (lane >> 2);
                float b0 = bias[c], b1v = bias[c + 1];
                *(u32*)&Dh[(size_t)r * 512 + c] =
                    pack2h(fmaxf(acc[fm][fn][0] + b0, 0.f), fmaxf(acc[fm][fn][1] + b1v, 0.f));
                *(u32*)&Dh[(size_t)(r + 8) * 512 + c] =
                    pack2h(fmaxf(acc[fm][fn][2] + b0, 0.f), fmaxf(acc[fm][fn][3] + b1v, 0.f));
            }
    } else {
        u16* hh = Hh[ping ^ 1];
        bool odd = lane & 1;
#pragma unroll
        for (int fm = 0; fm < 2; ++fm)
#pragma unroll
            for (int fn = 0; fn < NFR; ++fn) {
                float v0 = acc[fm][fn][0], v1 = acc[fm][fn][1];
                float v2 = acc[fm][fn][2], v3 = acc[fm][fn][3];
                float s0 = __shfl_xor_sync(0xFFFFFFFFu, v0, 1);
                float s1 = __shfl_xor_sync(0xFFFFFFFFu, v1, 1);
                float s2 = __shfl_xor_sync(0xFFFFFFFFu, v2, 1);
                float s3 = __shfl_xor_sync(0xFFFFFFFFu, v3, 1);
                int p = n0 + wn * (NFR * 8) + fn * 8 + (lane & 3) * 2;
                int u = p >> 2;
                int row = m0 + wm * 32 + fm * 16 + (lane >> 2) + (odd ? 8 : 0);
                float gi = odd ? s2 : v0;
                float gf = odd ? s3 : v1;
                float gg = odd ? v2 : s0;
                float go = odd ? v3 : s1;
                int pb = u * 4;
                gi += g_bgp[pb];     gf += g_bgp[pb + 1];
                gg += g_bgp[pb + 2]; go += g_bgp[pb + 3];
                float I = sigf(gi), F = sigf(gf), G = tanhf(gg), O = sigf(go);
                size_t ix = (size_t)row * 512 + u;
                float cn = F * g_c[ix] + I * G;
                float hn = O * tanhf(cn);
                g_c[ix] = cn;
                out[((size_t)row * T_ + t) * 512 + u] = hn;
                hh[ix] = h1(hn);
                Ch[ix] = h1(cn);
            }
    }
}

// ---------------- launch: 2 independent batch-half chains on 2 streams ----------------
extern "C" void kernel_launch(void* const* d_in, const int* in_sizes, int n_in,
                              void* d_out, int out_size)
{
    const float* sv  = (const float*)d_in[0];
    const float* W1  = (const float*)d_in[1];
    const float* b1  = (const float*)d_in[2];
    const float* W2  = (const float*)d_in[3];
    const float* b2  = (const float*)d_in[4];
    const float* W3  = (const float*)d_in[5];
    const float* b3  = (const float*)d_in[6];
    const float* Wih = (const float*)d_in[7];
    const float* Whh = (const float*)d_in[8];
    const float* bih = (const float*)d_in[9];
    const float* bhh = (const float*)d_in[10];
    float* out = (float*)d_out;

    const int SM01 = 3 * (32 * 128 + 8192);      // 36864
    const int SM2  = 2 * (128 * 128 + 8192);     // 49152

    static cudaStream_t s1 = nullptr;
    static cudaEvent_t ef = nullptr, ej = nullptr;
    if (s1 == nullptr) {
        cudaStreamCreateWithFlags(&s1, cudaStreamNonBlocking);
        cudaEventCreateWithFlags(&ef, cudaEventDisableTiming);
        cudaEventCreateWithFlags(&ej, cudaEventDisableTiming);
        cudaFuncSetAttribute(gemm_mma<0>, cudaFuncAttributeMaxDynamicSharedMemorySize, SM01);
        cudaFuncSetAttribute(gemm_mma<1>, cudaFuncAttributeMaxDynamicSharedMemorySize, SM01);
        cudaFuncSetAttribute(gemm_mma<2>, cudaFuncAttributeMaxDynamicSharedMemorySize, SM2);
    }

    prep_w<<<2048, 256>>>(W1, W3, Wih, Whh, bih, bhh);
    prep_z2<<<4096, 256>>>(sv, W2, b2);

    cudaEventRecord(ef, 0);
    cudaStreamWaitEvent(s1, ef, 0);

    dim3 gs(16, 8), gg(4, 32);
    for (int t = 0; t < T_; ++t) {
        int ping = t & 1;
        gemm_mma<0><<<gs, 128, SM01, 0>>>(0, ping, t, b1, out);
        gemm_mma<1><<<gs, 128, SM01, 0>>>(0, ping, t, b3, out);
        gemm_mma<2><<<gg, 256, SM2, 0>>>(0, ping, t, nullptr, out);
        gemm_mma<0><<<gs, 128, SM01, s1>>>(512, ping, t, b1, out);
        gemm_mma<1><<<gs, 128, SM01, s1>>>(512, ping, t, b3, out);
        gemm_mma<2><<<gg, 256, SM2, s1>>>(512, ping, t, nullptr, out);
    }

    cudaEventRecord(ej, s1);
    cudaStreamWaitEvent(0, ej, 0);
}

// round 16
// speedup vs baseline: 1.7709x; 1.0700x over previous
#include <cuda_runtime.h>
#include <cuda_fp16.h>
#include <cstdint>

#define B_ 1024
#define T_ 128

typedef unsigned short u16;
typedef uint32_t u32;

// ---------------- static device buffers (fp16, single-term weights) ----------------
__device__ __align__(16) u16 W1h[512 * 1024];
__device__ __align__(16) u16 W3h[512 * 1024];
__device__ __align__(16) u16 Wgh[2048 * 1024];   // [p=4i+q][k over x|h]
__device__ __align__(16) u16 Hh[2][B_ * 512];
__device__ __align__(16) u16 Ch[B_ * 512];
__device__ __align__(16) u16 Z1h[B_ * 512];
__device__ __align__(16) u16 Xh[B_ * 512];
__device__ __align__(16) u16 Z2h[(size_t)T_ * B_ * 512];
__device__ float g_c[B_ * 512];     // fp32 master cell state
__device__ float g_bgp[2048];

// ---------------- helpers ----------------
__device__ __forceinline__ u32 swz(u32 o) { return o ^ ((o >> 3) & 0x70); }
__device__ __forceinline__ u32 s2u(const void* p) {
    u32 a;
    asm("{ .reg .u64 t; cvta.to.shared.u64 t, %1; cvt.u32.u64 %0, t; }" : "=r"(a) : "l"(p));
    return a;
}
__device__ __forceinline__ void cp16(u32 dst, const void* src) {
    asm volatile("cp.async.cg.shared.global [%0], [%1], 16;" :: "r"(dst), "l"(src));
}
__device__ __forceinline__ void cp_commit() { asm volatile("cp.async.commit_group;" ::: "memory"); }
template <int N> __device__ __forceinline__ void cp_wait() {
    asm volatile("cp.async.wait_group %0;" :: "n"(N) : "memory");
}
__device__ __forceinline__ void ldsm4(u32* r, u32 a) {
    asm volatile("ldmatrix.sync.aligned.m8n8.x4.shared.b16 {%0,%1,%2,%3}, [%4];"
                 : "=r"(r[0]), "=r"(r[1]), "=r"(r[2]), "=r"(r[3]) : "r"(a));
}
__device__ __forceinline__ void hmma(float* c, const u32* a, u32 b0, u32 b1) {
    asm volatile("mma.sync.aligned.m16n8k16.row.col.f32.f16.f16.f32 "
                 "{%0,%1,%2,%3}, {%4,%5,%6,%7}, {%8,%9}, {%0,%1,%2,%3};"
                 : "+f"(c[0]), "+f"(c[1]), "+f"(c[2]), "+f"(c[3])
                 : "r"(a[0]), "r"(a[1]), "r"(a[2]), "r"(a[3]), "r"(b0), "r"(b1));
}
__device__ __forceinline__ u16 h1(float v) {
    __half x = __float2half_rn(v);
    return *(u16*)&x;
}
__device__ __forceinline__ u32 pack2h(float a, float b) {
    __half2 p = __floats2half2_rn(a, b);
    return *(u32*)&p;
}
__device__ __forceinline__ float sigf(float x) { return 1.f / (1.f + expf(-x)); }

// ---------------- prep: fp16 weights, biases, zero state ----------------
__global__ __launch_bounds__(256) void prep_w(
    const float* __restrict__ W1, const float* __restrict__ W3,
    const float* __restrict__ Wih, const float* __restrict__ Whh,
    const float* __restrict__ bih, const float* __restrict__ bhh)
{
    const int N1 = 524288, N2 = 1048576, N3 = N2 + 2097152;
    const int N4 = N3 + 2048, N5 = N4 + 524288, N6 = N5 + 524288;
    for (int idx = blockIdx.x * blockDim.x + threadIdx.x; idx < N6;
         idx += gridDim.x * blockDim.x) {
        if (idx < N2) {
            int j = (idx < N1) ? idx : idx - N1;
            float v = (idx < N1) ? W1[j] : W3[j];
            if (idx < N1) W1h[j] = h1(v); else W3h[j] = h1(v);
        } else if (idx < N3) {
            int j = idx - N2;
            int p = j >> 10, k = j & 1023;
            int r = (p & 3) * 512 + (p >> 2);
            float v = (k < 512) ? Wih[r * 512 + k] : Whh[r * 512 + (k - 512)];
            Wgh[j] = h1(v);
        } else if (idx < N4) {
            int p = idx - N3, i = p >> 2, q = p & 3;
            g_bgp[p] = bih[q * 512 + i] + bhh[q * 512 + i];
        } else if (idx < N5) {
            int j = idx - N4;
            int sel = j >> 18, w = j & 262143;
            u16* b = (sel == 0) ? Hh[0] : Ch;
            *(u32*)&b[w * 2] = 0u;
        } else g_c[idx - N5] = 0.f;
    }
}

// ---------------- prep: z2 for all t (fp16) ----------------
__global__ __launch_bounds__(256) void prep_z2(
    const float* __restrict__ sv, const float* __restrict__ W2, const float* __restrict__ b2)
{
    __shared__ float W2s[10 * 512];
    __shared__ float svs[32 * 10];
    int tid = threadIdx.x;
    for (int idx = tid; idx < 5120; idx += 256)
        W2s[(idx % 10) * 512 + idx / 10] = W2[idx];
    int u0 = blockIdx.x * 32;
    for (int idx = tid; idx < 320; idx += 256) svs[idx] = sv[u0 * 10 + idx];
    __syncthreads();
    int f0 = tid * 2;
    float c0 = b2[f0], c1 = b2[f0 + 1];
    for (int p = 0; p < 32; ++p) {
        int u = u0 + p, bb = u >> 7, tt = u & 127;
        float a0 = c0, a1 = c1;
#pragma unroll
        for (int j = 0; j < 10; ++j) {
            float s = svs[p * 10 + j];
            a0 += s * W2s[j * 512 + f0];
            a1 += s * W2s[j * 512 + f0 + 1];
        }
        size_t off = (size_t)tt * 524288 + (size_t)bb * 512 + f0;
        *(u32*)&Z2h[off] = pack2h(fmaxf(a0, 0.f), fmaxf(a1, 0.f));
    }
}

// ---------------- single-term fp16 HMMA GEMM, K=128 per stage (8 stages) ----------------
// MODE 0: z1 = relu([h|c] @ W1^T + b1)      tile 32x64, 128thr, 3-stage, grid (32,8)
// MODE 1: x  = relu([z1|z2_t] @ W3^T + b3)  tile 32x64, 128thr, 3-stage, grid (32,8)
// MODE 2: gates(interleaved) + LSTM cell    tile 128x64, 256thr, 2-stage, grid (8,32)
template <int MODE>
__global__ __launch_bounds__((MODE == 2) ? 256 : 128, 1) void gemm_mma(
    int ping, int t, const float* __restrict__ bias, float* __restrict__ out)
{
    constexpr int MT  = (MODE == 2) ? 128 : 32;
    constexpr int TH  = (MODE == 2) ? 256 : 128;
    constexpr int NWARP = TH / 32;
    constexpr int WMW = (MODE == 2) ? 4 : 1;
    constexpr int WNW = NWARP / WMW;
    constexpr int NFR = 8 / WNW;
    constexpr int NSTAGE = (MODE == 2) ? 2 : 3;
    constexpr u32 A_IMG = MT * 128;           // bytes per 64-k half-image of A
    constexpr u32 B_IMG = 64 * 128;           // bytes per 64-k half-image of B
    constexpr u32 OB = 2 * A_IMG;             // B images offset
    constexpr u32 STAGE = 2 * A_IMG + 2 * B_IMG;

    extern __shared__ __align__(16) unsigned char smem[];
    const u32 sb = s2u(smem);
    const int tid = threadIdx.x, lane = tid & 31, wid = tid >> 5;
    const int m0 = blockIdx.x * MT, n0 = blockIdx.y * 64;
    const int wm = wid % WMW, wn = wid / WMW;

    const u16 *A1, *A2, *Wh;
    if (MODE == 0) { A1 = Hh[ping]; A2 = Ch; Wh = W1h; }
    else if (MODE == 1) {
        A1 = Z1h; A2 = Z2h + (size_t)t * 524288; Wh = W3h;
    } else { A1 = Xh; A2 = Hh[ping]; Wh = Wgh; }

    float acc[2][NFR][4];
#pragma unroll
    for (int a = 0; a < 2; ++a)
#pragma unroll
        for (int b = 0; b < NFR; ++b)
#pragma unroll
            for (int q = 0; q < 4; ++q) acc[a][b][q] = 0.f;

    // stage s covers k in [s*128, s*128+128): two 64-k half-images
    auto load_stage = [&](int s) {
        int buf = s % NSTAGE, k0 = s * 128;
        u32 base = sb + (u32)buf * STAGE;
#pragma unroll
        for (int i = tid; i < MT * 16; i += TH) {
            int row = i >> 4, q = i & 15, half = q >> 3, c16 = q & 7;
            int ks = k0 + half * 64;
            const u16* sa = (ks < 512) ? A1 : A2;
            cp16(base + (u32)half * A_IMG + swz((u32)(row * 128 + c16 * 16)),
                 sa + (size_t)(m0 + row) * 512 + (ks & 511) + c16 * 8);
        }
#pragma unroll
        for (int i = tid; i < 1024; i += TH) {
            int row = i >> 4, q = i & 15, half = q >> 3, c16 = q & 7;
            cp16(base + OB + (u32)half * B_IMG + swz((u32)(row * 128 + c16 * 16)),
                 Wh + (size_t)(n0 + row) * 1024 + k0 + half * 64 + c16 * 8);
        }
    };

#pragma unroll
    for (int s = 0; s < NSTAGE - 1; ++s) { load_stage(s); cp_commit(); }

    const int arow = wm * 32 + (lane & 15);
    const int brow = wn * (NFR * 8) + (lane & 15);
    const u32 hi16 = (u32)((lane >> 4) * 16);

    for (int s = 0; s < 8; ++s) {
        cp_wait<NSTAGE - 2>();
        __syncthreads();
        if (s + NSTAGE - 1 < 8) load_stage(s + NSTAGE - 1);
        cp_commit();   // unconditional: tail-drain-safe group alignment
        u32 base = sb + (u32)(s % NSTAGE) * STAGE;

        if (MODE == 2) {
#pragma unroll
            for (int kk = 0; kk < 8; ++kk) {
                u32 Ab = base + (u32)(kk >> 2) * A_IMG;
                u32 Bb = base + OB + (u32)(kk >> 2) * B_IMG;
                u32 kb = (u32)((kk & 3) * 32) + hi16;
                u32 Ar[2][4], Br[2][4];
#pragma unroll
                for (int fm = 0; fm < 2; ++fm)
                    ldsm4(Ar[fm], Ab + swz((u32)((arow + fm * 16) * 128) + kb));
#pragma unroll
                for (int nf = 0; nf < 2; ++nf)
                    ldsm4(Br[nf], Bb + swz((u32)((brow + nf * 16) * 128) + kb));
#pragma unroll
                for (int fm = 0; fm < 2; ++fm)
#pragma unroll
                    for (int fn = 0; fn < 4; ++fn)
                        hmma(acc[fm][fn], Ar[fm],
                             Br[fn >> 1][fn & 1], Br[fn >> 1][(fn & 1) + 2]);
            }
        } else {
            u32 Af[2][2][4], Bf[2][4];
#define LDFRAG(bf, kk) do { \
            u32 Ab_ = base + (u32)((kk) >> 2) * A_IMG; \
            u32 Bb_ = base + OB + (u32)((kk) >> 2) * B_IMG; \
            u32 kb = (u32)(((kk) & 3) * 32) + hi16; \
            ldsm4(Af[bf][0], Ab_ + swz((u32)(arow * 128) + kb)); \
            ldsm4(Af[bf][1], Ab_ + swz((u32)((arow + 16) * 128) + kb)); \
            ldsm4(Bf[bf], Bb_ + swz((u32)(brow * 128) + kb)); \
        } while (0)
            LDFRAG(0, 0);
#pragma unroll
            for (int kk = 0; kk < 8; ++kk) {
                const int cur = kk & 1;
                if (kk < 7) LDFRAG(cur ^ 1, kk + 1);
#pragma unroll
                for (int fm = 0; fm < 2; ++fm)
#pragma unroll
                    for (int fn = 0; fn < 2; ++fn)
                        hmma(acc[fm][fn], Af[cur][fm], Bf[cur][fn], Bf[cur][fn + 2]);
            }
#undef LDFRAG
        }
    }

    // ---------------- epilogue ----------------
    if (MODE < 2) {
        u16* Dh = (MODE == 0) ? Z1h : Xh;
#pragma unroll
        for (int fm = 0; fm < 2; ++fm)
#pragma unroll
            for (int fn = 0; fn < NFR; ++fn) {
                int c = n0 + wn * (NFR * 8) + fn * 8 + (lane & 3) * 2;
                int r = m0 + wm * 32 + fm * 16 + (lane >> 2);
                float b0 = bias[c], b1v = bias[c + 1];
                *(u32*)&Dh[(size_t)r * 512 + c] =
                    pack2h(fmaxf(acc[fm][fn][0] + b0, 0.f), fmaxf(acc[fm][fn][1] + b1v, 0.f));
                *(u32*)&Dh[(size_t)(r + 8) * 512 + c] =
                    pack2h(fmaxf(acc[fm][fn][2] + b0, 0.f), fmaxf(acc[fm][fn][3] + b1v, 0.f));
            }
    } else {
        u16* hh = Hh[ping ^ 1];
        bool odd = lane & 1;
#pragma unroll
        for (int fm = 0; fm < 2; ++fm)
#pragma unroll
            for (int fn = 0; fn < NFR; ++fn) {
                float v0 = acc[fm][fn][0], v1 = acc[fm][fn][1];
                float v2 = acc[fm][fn][2], v3 = acc[fm][fn][3];
                float s0 = __shfl_xor_sync(0xFFFFFFFFu, v0, 1);
                float s1 = __shfl_xor_sync(0xFFFFFFFFu, v1, 1);
                float s2 = __shfl_xor_sync(0xFFFFFFFFu, v2, 1);
                float s3 = __shfl_xor_sync(0xFFFFFFFFu, v3, 1);
                int p = n0 + wn * (NFR * 8) + fn * 8 + (lane & 3) * 2;
                int u = p >> 2;
                int row = m0 + wm * 32 + fm * 16 + (lane >> 2) + (odd ? 8 : 0);
                float gi = odd ? s2 : v0;
                float gf = odd ? s3 : v1;
                float gg = odd ? v2 : s0;
                float go = odd ? v3 : s1;
                int pb = u * 4;
                gi += g_bgp[pb];     gf += g_bgp[pb + 1];
                gg += g_bgp[pb + 2]; go += g_bgp[pb + 3];
                float I = sigf(gi), F = sigf(gf), G = tanhf(gg), O = sigf(go);
                size_t ix = (size_t)row * 512 + u;
                float cn = F * g_c[ix] + I * G;
                float hn = O * tanhf(cn);
                g_c[ix] = cn;
                out[((size_t)row * T_ + t) * 512 + u] = hn;
                hh[ix] = h1(hn);
                Ch[ix] = h1(cn);
            }
    }
}

// ---------------- launch: 3 full-batch kernels per step ----------------
extern "C" void kernel_launch(void* const* d_in, const int* in_sizes, int n_in,
                              void* d_out, int out_size)
{
    const float* sv  = (const float*)d_in[0];
    const float* W1  = (const float*)d_in[1];
    const float* b1  = (const float*)d_in[2];
    const float* W2  = (const float*)d_in[3];
    const float* b2  = (const float*)d_in[4];
    const float* W3  = (const float*)d_in[5];
    const float* b3  = (const float*)d_in[6];
    const float* Wih = (const float*)d_in[7];
    const float* Whh = (const float*)d_in[8];
    const float* bih = (const float*)d_in[9];
    const float* bhh = (const float*)d_in[10];
    float* out = (float*)d_out;

    const int SM01 = 3 * (2 * 32 * 128 + 2 * 64 * 128);    // 3*24576 = 73728
    const int SM2  = 2 * (2 * 128 * 128 + 2 * 64 * 128);   // 2*49152 = 98304

    static bool init = false;
    if (!init) {
        init = true;
        cudaFuncSetAttribute(gemm_mma<0>, cudaFuncAttributeMaxDynamicSharedMemorySize, SM01);
        cudaFuncSetAttribute(gemm_mma<1>, cudaFuncAttributeMaxDynamicSharedMemorySize, SM01);
        cudaFuncSetAttribute(gemm_mma<2>, cudaFuncAttributeMaxDynamicSharedMemorySize, SM2);
    }

    prep_w<<<2048, 256>>>(W1, W3, Wih, Whh, bih, bhh);
    prep_z2<<<4096, 256>>>(sv, W2, b2);

    dim3 gs(32, 8), gg(8, 32);
    for (int t = 0; t < T_; ++t) {
        int ping = t & 1;
        gemm_mma<0><<<gs, 128, SM01>>>(ping, t, b1, out);
        gemm_mma<1><<<gs, 128, SM01>>>(ping, t, b3, out);
        gemm_mma<2><<<gg, 256, SM2>>>(ping, t, nullptr, out);
    }
}